// round 2
// baseline (speedup 1.0000x reference)
#include <cuda_runtime.h>

#define EPSV 1e-5f

// ---- scratch: __device__ globals (zero-init; padded borders rely on it) ----
__device__ float g_z[16*320*256];      // pooled x
__device__ float g_gm[16*32];          // GN1 mean
__device__ float g_gr[16*32];          // GN1 rstd
__device__ float g_z1p[32*16*8*256];   // conv1 partials per channel-chunk
__device__ float g_z1[16*8*256];       // conv1 out (residual base)
__device__ float g_qkv[16*24*256];
__device__ float g_att[16*8*256];
__device__ float g_z3[16*8*256];       // post-MLP
__device__ float g_apad[16*8*18*18];   // silu(gn2) on 16x16, zero-padded border
__device__ float g_kw[320*8*36];       // collapsed 6x6 transposed-conv weights

__device__ __forceinline__ float siluf(float x){ return x/(1.0f+__expf(-x)); }

__device__ __forceinline__ float redsum256(float v, float* sb){
    #pragma unroll
    for(int o=16;o;o>>=1) v += __shfl_xor_sync(0xffffffffu, v, o);
    if((threadIdx.x&31)==0) sb[threadIdx.x>>5]=v;
    __syncthreads();
    float r = sb[0]+sb[1]+sb[2]+sb[3]+sb[4]+sb[5]+sb[6]+sb[7];
    __syncthreads();
    return r;
}

// ---- K1: 4x4 average pool ----
__global__ void k_pool(const float* __restrict__ x){
    int plane = blockIdx.x;            // b*320 + c
    int t = threadIdx.x;               // 256 -> 16x16 out plane
    int Y = t>>4, X = t&15;
    const float4* xr = (const float4*)(x + (size_t)plane*4096);
    float s = 0.f;
    #pragma unroll
    for(int r=0;r<4;r++){
        float4 v = xr[(4*Y+r)*16 + X];
        s += v.x+v.y+v.z+v.w;
    }
    g_z[plane*256 + t] = s*(1.0f/16.0f);
}

// ---- K2: GN(32) stats on pooled z ----
__global__ void k_gstat(){
    __shared__ float sb[8];
    int b = blockIdx.x>>5, g = blockIdx.x&31;
    int t = threadIdx.x;
    float s=0.f, s2=0.f;
    #pragma unroll
    for(int i=0;i<10;i++){
        float v = g_z[((b*320 + g*10 + i)<<8) + t];
        s += v; s2 += v*v;
    }
    s  = redsum256(s,  sb);
    s2 = redsum256(s2, sb);
    if(t==0){
        float m = s*(1.0f/2560.0f);
        float var = s2*(1.0f/2560.0f) - m*m;
        g_gm[blockIdx.x] = m;
        g_gr[blockIdx.x] = rsqrtf(var + EPSV);
    }
}

// ---- K3: conv1 (320->8, 3x3 SAME, 16x16), GN1+SiLU fused; per-group partials ----
__global__ void k_conv1(const float* __restrict__ g1, const float* __restrict__ b1,
                        const float* __restrict__ w1){
    __shared__ float sp[324];   // 18x18 padded plane
    __shared__ float sw[720];   // [8 o][10 ci][9]
    int j = blockIdx.x, b = blockIdx.y;
    int t = threadIdx.x;        // 64
    for(int i=t;i<720;i+=64){
        int o = i/90, rr = i-o*90, ci = rr/9, k = rr-ci*9;
        sw[i] = w1[o*2880 + (j*10+ci)*9 + k];
    }
    float m = g_gm[b*32+j], rs = g_gr[b*32+j];
    int y = t>>2, xg = t&3;     // row y, 4 consecutive x outputs
    float acc[8][4];
    #pragma unroll
    for(int o=0;o<8;o++){ acc[o][0]=acc[o][1]=acc[o][2]=acc[o][3]=0.f; }
    for(int ci=0;ci<10;ci++){
        int c = j*10+ci;
        float gam = g1[c], bet = b1[c];
        __syncthreads();
        for(int i=t;i<324;i+=64){
            int r18 = i/18, c18 = i-r18*18;
            float val = 0.f;
            if(r18>=1 && r18<=16 && c18>=1 && c18<=16){
                float v = g_z[((b*320+c)<<8) + (r18-1)*16 + (c18-1)];
                val = siluf((v-m)*rs*gam + bet);
            }
            sp[i]=val;
        }
        __syncthreads();
        float a[3][6];
        #pragma unroll
        for(int dy=0;dy<3;dy++)
            #pragma unroll
            for(int dx=0;dx<6;dx++) a[dy][dx] = sp[(y+dy)*18 + 4*xg + dx];
        #pragma unroll
        for(int o=0;o<8;o++){
            #pragma unroll
            for(int dy=0;dy<3;dy++)
                #pragma unroll
                for(int dx=0;dx<3;dx++){
                    float w = sw[(o*10+ci)*9 + dy*3+dx];
                    #pragma unroll
                    for(int p=0;p<4;p++) acc[o][p] += a[dy][dx+p]*w;
                }
        }
    }
    #pragma unroll
    for(int o=0;o<8;o++)
        #pragma unroll
        for(int p=0;p<4;p++)
            g_z1p[(((j*16+b)*8+o)<<8) + y*16 + 4*xg + p] = acc[o][p];
}

// ---- K4: merge conv1 partials + bias ----
__global__ void k_merge(const float* __restrict__ bc1){
    int idx = blockIdx.x*256 + threadIdx.x;    // 32768 = [b][o][256]
    int rem = idx&2047, o = rem>>8;
    float s = bc1[o];
    int b = idx>>11, px = idx&255;
    #pragma unroll
    for(int jj=0;jj<32;jj++)
        s += g_z1p[(((jj*16+b)*8+o)<<8) + px];
    g_z1[idx] = s;
}

// ---- K5: per-channel GN + 1x1 qkv ----
__global__ void k_qkv(const float* __restrict__ ga, const float* __restrict__ ba,
                      const float* __restrict__ wq, const float* __restrict__ bq){
    __shared__ float sb[8];
    __shared__ float swq[192];
    __shared__ float sm[8], sr[8];
    int b = blockIdx.x, t = threadIdx.x;
    if(t<192) swq[t] = wq[t];
    float zv[8];
    #pragma unroll
    for(int c=0;c<8;c++) zv[c] = g_z1[(b*8+c)*256 + t];
    #pragma unroll
    for(int c=0;c<8;c++){
        float s  = redsum256(zv[c], sb);
        float s2 = redsum256(zv[c]*zv[c], sb);
        if(t==0){
            float m = s*(1.f/256.f);
            sm[c]=m; sr[c]=rsqrtf(s2*(1.f/256.f)-m*m+EPSV);
        }
    }
    __syncthreads();
    float nv[8];
    #pragma unroll
    for(int c=0;c<8;c++) nv[c] = (zv[c]-sm[c])*sr[c]*ga[c] + ba[c];
    #pragma unroll
    for(int jj=0;jj<24;jj++){
        float s = bq[jj];
        #pragma unroll
        for(int c=0;c<8;c++) s += swq[jj*8+c]*nv[c];
        g_qkv[(b*24+jj)*256 + t] = s;
    }
}

// ---- K6: attention, one block per (batch, head), dh=2, n=256 ----
__global__ void k_attn(){
    __shared__ float2 sk[256], sv[256];
    int b = blockIdx.x>>2, h = blockIdx.x&3;
    int t = threadIdx.x;
    const float* base = g_qkv + b*24*256;
    float q0 = base[(2*h  )*256+t];
    float q1 = base[(2*h+1)*256+t];
    sk[t] = make_float2(base[( 8+2*h)*256+t], base[( 9+2*h)*256+t]);
    sv[t] = make_float2(base[(16+2*h)*256+t], base[(17+2*h)*256+t]);
    const float scale = 0.7071067811865475f;   // dh^-0.5
    q0*=scale; q1*=scale;
    __syncthreads();
    float mx = -1e30f;
    #pragma unroll 8
    for(int m=0;m<256;m++){
        float2 kk = sk[m];
        mx = fmaxf(mx, q0*kk.x + q1*kk.y);
    }
    float den=0.f, a0=0.f, a1=0.f;
    #pragma unroll 8
    for(int m=0;m<256;m++){
        float2 kk = sk[m];
        float e = __expf(q0*kk.x + q1*kk.y - mx);
        float2 vv = sv[m];
        den += e;
        a0 += e*vv.x; a1 += e*vv.y;
    }
    float inv = 1.0f/den;
    g_att[(b*8 + 2*h  )*256 + t] = a0*inv;
    g_att[(b*8 + 2*h+1)*256 + t] = a1*inv;
}

// ---- K7: proj + residual + LayerNorm + MLP(exact gelu) + residual ----
__global__ void k_mlp(const float* __restrict__ wp, const float* __restrict__ bp,
                      const float* __restrict__ lng, const float* __restrict__ lnb,
                      const float* __restrict__ wf1, const float* __restrict__ bf1,
                      const float* __restrict__ wf2, const float* __restrict__ bf2){
    int b = blockIdx.x, t = threadIdx.x;
    float ao[8], z2[8];
    #pragma unroll
    for(int c=0;c<8;c++) ao[c] = g_att[(b*8+c)*256+t];
    #pragma unroll
    for(int c=0;c<8;c++){
        float s = bp[c] + g_z1[(b*8+c)*256+t];
        #pragma unroll
        for(int d=0;d<8;d++) s += wp[c*8+d]*ao[d];
        z2[c]=s;
    }
    float mu=0.f;
    #pragma unroll
    for(int c=0;c<8;c++) mu += z2[c];
    mu *= 0.125f;
    float var=0.f;
    #pragma unroll
    for(int c=0;c<8;c++){ float d=z2[c]-mu; var += d*d; }
    float rs = rsqrtf(var*0.125f + EPSV);
    float ln[8];
    #pragma unroll
    for(int c=0;c<8;c++) ln[c] = (z2[c]-mu)*rs*lng[c] + lnb[c];
    float hg[16];
    #pragma unroll
    for(int jj=0;jj<16;jj++){
        float s = bf1[jj];
        #pragma unroll
        for(int c=0;c<8;c++) s += wf1[jj*8+c]*ln[c];
        hg[jj] = 0.5f*s*(1.0f + erff(s*0.7071067811865475f));
    }
    #pragma unroll
    for(int c=0;c<8;c++){
        float s = z2[c] + bf2[c];
        #pragma unroll
        for(int jj=0;jj<16;jj++) s += wf2[c*16+jj]*hg[jj];
        g_z3[(b*8+c)*256+t] = s;
    }
}

// ---- K8: GN2 (stats on 16x16 == stats on upsampled) + SiLU -> padded plane ----
__global__ void k_apad(const float* __restrict__ g2, const float* __restrict__ b2){
    __shared__ float sb[8];
    __shared__ float sm[8], sr[8];
    int b = blockIdx.x, t = threadIdx.x;
    float v[8];
    #pragma unroll
    for(int c=0;c<8;c++) v[c] = g_z3[(b*8+c)*256+t];
    #pragma unroll
    for(int c=0;c<8;c++){
        float s  = redsum256(v[c], sb);
        float s2 = redsum256(v[c]*v[c], sb);
        if(t==0){
            float m = s*(1.f/256.f);
            sm[c]=m; sr[c]=rsqrtf(s2*(1.f/256.f)-m*m+EPSV);
        }
    }
    __syncthreads();
    int Y=t>>4, X=t&15;
    #pragma unroll
    for(int c=0;c<8;c++){
        float a = siluf((v[c]-sm[c])*sr[c]*g2[c] + b2[c]);
        g_apad[(b*8+c)*324 + (Y+1)*18 + (X+1)] = a;
    }
}

// ---- K9: collapse 3x3 conv weights into 6x6 stride-4 transposed-conv kernel ----
__global__ void k_wt(const float* __restrict__ w2){
    int idx = blockIdx.x*256+threadIdx.x;
    if(idx>=92160) return;
    int o = idx/288, r = idx-o*288, c = r/36, q = r-c*36, ky = q/6, kx = q-ky*6;
    int dy0 = max(0, 2-ky), dy1 = min(2, 5-ky);
    int dx0 = max(0, 2-kx), dx1 = min(2, 5-kx);
    float s=0.f;
    for(int dy=dy0;dy<=dy1;dy++)
        for(int dx=dx0;dx<=dx1;dx++)
            s += w2[o*72 + c*9 + dy*3 + dx];
    g_kw[idx] = s;
}

// ---- K10: fused upsample+conv2 (8->320) as stride-4 transposed conv ----
// grid (80 o-groups of 4, 16 b) x 256 thr; thread = (ol, cell-row Yq, 4-cell strip Xs)
__global__ void __launch_bounds__(256) k_conv2(const float* __restrict__ bc2,
                                               float* __restrict__ out){
    __shared__ float sa[2592];   // a_pad[b]: 8 x 18 x 18
    __shared__ float sw[1152];   // K6 for 4 o-channels: [4][8][36]
    int og = blockIdx.x, b = blockIdx.y;
    int t = threadIdx.x;
    for(int i=t;i<2592;i+=256) sa[i] = g_apad[b*2592+i];
    for(int i=t;i<1152;i+=256) sw[i] = g_kw[og*1152+i];
    __syncthreads();
    int ol = t>>6, u = t&63, Yq = u>>2, Xs = u&3;
    int o = og*4+ol;
    float bias = bc2[o];
    float acc[64];
    #pragma unroll
    for(int i=0;i<64;i++) acc[i]=bias;
    // per-ky/kx routing (derived from stride-4 footprint)
    const int RYof[6]={3,0,1,2,3,0};   // output sub-row
    const int RWof[6]={2,1,1,1,1,0};   // aw row
    const int XL0[6] ={3,0,1,2,3,0};   // output col base (stride 4)
    const int SCB[6] ={2,1,1,1,1,0};   // aw col base (stride 1 over j)
    #pragma unroll
    for(int c=0;c<8;c++){
        float aw[3][6];
        #pragma unroll
        for(int r=0;r<3;r++)
            #pragma unroll
            for(int cc=0;cc<6;cc++)
                aw[r][cc] = sa[(c*18 + Yq + r)*18 + 4*Xs + cc];
        const float* wc = &sw[(ol*8 + c)*36];
        #pragma unroll
        for(int ky=0;ky<6;ky++){
            int ry = RYof[ky], riw = RWof[ky];
            #pragma unroll
            for(int kx=0;kx<6;kx++){
                float w = wc[ky*6+kx];
                int xl0 = XL0[kx], scb = SCB[kx];
                #pragma unroll
                for(int j=0;j<4;j++)
                    acc[ry*16 + xl0 + 4*j] += w * aw[riw][scb + j];
            }
        }
    }
    float4* ob = (float4*)(out + ((size_t)(b*320 + o)*64 + 4*Yq)*64 + 16*Xs);
    #pragma unroll
    for(int ry=0;ry<4;ry++)
        #pragma unroll
        for(int js=0;js<4;js++)
            ob[ry*16 + js] = make_float4(acc[ry*16+js*4], acc[ry*16+js*4+1],
                                         acc[ry*16+js*4+2], acc[ry*16+js*4+3]);
}

extern "C" void kernel_launch(void* const* d_in, const int* in_sizes, int n_in,
                              void* d_out, int out_size) {
    const float* x   = (const float*)d_in[0];
    const float* g1  = (const float*)d_in[1];
    const float* b1  = (const float*)d_in[2];
    const float* w1  = (const float*)d_in[3];
    const float* bc1 = (const float*)d_in[4];
    const float* ga  = (const float*)d_in[5];
    const float* ba  = (const float*)d_in[6];
    const float* wq  = (const float*)d_in[7];
    const float* bq  = (const float*)d_in[8];
    const float* wp  = (const float*)d_in[9];
    const float* bp  = (const float*)d_in[10];
    const float* lng = (const float*)d_in[11];
    const float* lnb = (const float*)d_in[12];
    const float* wf1 = (const float*)d_in[13];
    const float* bf1 = (const float*)d_in[14];
    const float* wf2 = (const float*)d_in[15];
    const float* bf2 = (const float*)d_in[16];
    const float* g2  = (const float*)d_in[17];
    const float* b2  = (const float*)d_in[18];
    const float* w2  = (const float*)d_in[19];
    const float* bc2 = (const float*)d_in[20];
    float* out = (float*)d_out;

    k_wt   <<<360, 256>>>(w2);
    k_pool <<<5120, 256>>>(x);
    k_gstat<<<512, 256>>>();
    k_conv1<<<dim3(32,16), 64>>>(g1, b1, w1);
    k_merge<<<128, 256>>>(bc1);
    k_qkv  <<<16, 256>>>(ga, ba, wq, bq);
    k_attn <<<64, 256>>>();
    k_mlp  <<<16, 256>>>(wp, bp, lng, lnb, wf1, bf1, wf2, bf2);
    k_apad <<<16, 256>>>(g2, b2);
    k_conv2<<<dim3(80,16), 256>>>(bc2, out);
}

// round 3
// speedup vs baseline: 1.0561x; 1.0561x over previous
#include <cuda_runtime.h>

#define EPSV 1e-5f

// ---- scratch: __device__ globals (zero-init) ----
__device__ float g_z[16*320*256];      // pooled x
__device__ float g_gm[16*32];          // GN1 mean
__device__ float g_gr[16*32];          // GN1 rstd
__device__ float g_z1p[32*16*8*256];   // conv1 partials per channel-chunk
__device__ float g_z1[16*8*256];       // conv1 out (residual base)
__device__ float g_qkv[16*24*256];
__device__ float g_att[16*8*256];
__device__ float g_apad[16*8*18*18];   // silu(gn2) on 16x16, zero-padded border
__device__ float g_kw[320*8*36];       // collapsed 6x6 transposed-conv weights

__device__ __forceinline__ float siluf(float x){ return x/(1.0f+__expf(-x)); }

__device__ __forceinline__ float redsum256(float v, float* sb){
    #pragma unroll
    for(int o=16;o;o>>=1) v += __shfl_xor_sync(0xffffffffu, v, o);
    if((threadIdx.x&31)==0) sb[threadIdx.x>>5]=v;
    __syncthreads();
    float r = sb[0]+sb[1]+sb[2]+sb[3]+sb[4]+sb[5]+sb[6]+sb[7];
    __syncthreads();
    return r;
}

// ---- K1: 4x4 average pool ----
__global__ void k_pool(const float* __restrict__ x){
    int plane = blockIdx.x;            // b*320 + c
    int t = threadIdx.x;               // 256 -> 16x16 out plane
    int Y = t>>4, X = t&15;
    const float4* xr = (const float4*)(x + (size_t)plane*4096);
    float s = 0.f;
    #pragma unroll
    for(int r=0;r<4;r++){
        float4 v = xr[(4*Y+r)*16 + X];
        s += v.x+v.y+v.z+v.w;
    }
    g_z[plane*256 + t] = s*(1.0f/16.0f);
}

// ---- K2: GN(32) stats on pooled z ----
__global__ void k_gstat(){
    __shared__ float sb[8];
    int b = blockIdx.x>>5, g = blockIdx.x&31;
    int t = threadIdx.x;
    float s=0.f, s2=0.f;
    #pragma unroll
    for(int i=0;i<10;i++){
        float v = g_z[((b*320 + g*10 + i)<<8) + t];
        s += v; s2 += v*v;
    }
    s  = redsum256(s,  sb);
    s2 = redsum256(s2, sb);
    if(t==0){
        float m = s*(1.0f/2560.0f);
        float var = s2*(1.0f/2560.0f) - m*m;
        g_gm[blockIdx.x] = m;
        g_gr[blockIdx.x] = rsqrtf(var + EPSV);
    }
}

// ---- K3: conv1 (320->8, 3x3 SAME, 16x16), GN1+SiLU fused; per-group partials ----
// grid (32 groups, 16 b) x 256 thr; thread = output pixel, 8 o-channel accs
__global__ void __launch_bounds__(256) k_conv1(const float* __restrict__ g1,
                                               const float* __restrict__ b1,
                                               const float* __restrict__ w1){
    __shared__ float sp[3240];   // 10 channels x 18x18 padded
    __shared__ float sw[720];    // [ci][o][9]
    int j = blockIdx.x, b = blockIdx.y;
    int t = threadIdx.x;
    float m = g_gm[b*32+j], rs = g_gr[b*32+j];
    for(int i=t;i<720;i+=256){
        int ci = i/72, r = i-ci*72, o = r/9, k = r-o*9;
        sw[i] = w1[o*2880 + (j*10+ci)*9 + k];
    }
    for(int i=t;i<3240;i+=256){
        int ci = i/324, p = i-ci*324;
        int r18 = p/18, c18 = p-r18*18;
        float val = 0.f;
        if(r18>=1 && r18<=16 && c18>=1 && c18<=16){
            int c = j*10+ci;
            float v = g_z[((b*320+c)<<8) + (r18-1)*16 + (c18-1)];
            val = siluf((v-m)*rs*g1[c] + b1[c]);
        }
        sp[i]=val;
    }
    __syncthreads();
    int Y = t>>4, X = t&15;
    float acc[8];
    #pragma unroll
    for(int o=0;o<8;o++) acc[o]=0.f;
    #pragma unroll
    for(int ci=0;ci<10;ci++){
        float a[9];
        #pragma unroll
        for(int dy=0;dy<3;dy++)
            #pragma unroll
            for(int dx=0;dx<3;dx++)
                a[dy*3+dx] = sp[ci*324 + (Y+dy)*18 + (X+dx)];
        const float* wc = &sw[ci*72];
        #pragma unroll
        for(int o=0;o<8;o++){
            #pragma unroll
            for(int k=0;k<9;k++) acc[o] += a[k]*wc[o*9+k];
        }
    }
    #pragma unroll
    for(int o=0;o<8;o++)
        g_z1p[(((j*16+b)*8+o)<<8) + t] = acc[o];
}

// ---- K4: merge partials + bias + per-channel GN + 1x1 qkv (fused) ----
__global__ void k_qkv(const float* __restrict__ bc1,
                      const float* __restrict__ ga, const float* __restrict__ ba,
                      const float* __restrict__ wq, const float* __restrict__ bq){
    __shared__ float sb[8];
    __shared__ float swq[192];
    __shared__ float sm[8], sr[8];
    int b = blockIdx.x, t = threadIdx.x;
    if(t<192) swq[t] = wq[t];
    float zv[8];
    #pragma unroll
    for(int c=0;c<8;c++){
        float s = bc1[c];
        #pragma unroll
        for(int jj=0;jj<32;jj++)
            s += g_z1p[(((jj*16+b)*8+c)<<8) + t];
        zv[c]=s;
        g_z1[(b*8+c)*256 + t] = s;
    }
    #pragma unroll
    for(int c=0;c<8;c++){
        float s  = redsum256(zv[c], sb);
        float s2 = redsum256(zv[c]*zv[c], sb);
        if(t==0){
            float mm = s*(1.f/256.f);
            sm[c]=mm; sr[c]=rsqrtf(s2*(1.f/256.f)-mm*mm+EPSV);
        }
    }
    __syncthreads();
    float nv[8];
    #pragma unroll
    for(int c=0;c<8;c++) nv[c] = (zv[c]-sm[c])*sr[c]*ga[c] + ba[c];
    #pragma unroll
    for(int jj=0;jj<24;jj++){
        float s = bq[jj];
        #pragma unroll
        for(int c=0;c<8;c++) s += swq[jj*8+c]*nv[c];
        g_qkv[(b*24+jj)*256 + t] = s;
    }
}

// ---- K5: attention, one block per (batch, head), dh=2, n=256 ----
__global__ void k_attn(){
    __shared__ float2 sk[256], sv[256];
    int b = blockIdx.x>>2, h = blockIdx.x&3;
    int t = threadIdx.x;
    const float* base = g_qkv + b*24*256;
    float q0 = base[(2*h  )*256+t];
    float q1 = base[(2*h+1)*256+t];
    sk[t] = make_float2(base[( 8+2*h)*256+t], base[( 9+2*h)*256+t]);
    sv[t] = make_float2(base[(16+2*h)*256+t], base[(17+2*h)*256+t]);
    const float scale = 0.7071067811865475f;   // dh^-0.5
    q0*=scale; q1*=scale;
    __syncthreads();
    float mx = -1e30f;
    #pragma unroll 8
    for(int m=0;m<256;m++){
        float2 kk = sk[m];
        mx = fmaxf(mx, q0*kk.x + q1*kk.y);
    }
    float den=0.f, a0=0.f, a1=0.f;
    #pragma unroll 8
    for(int m=0;m<256;m++){
        float2 kk = sk[m];
        float e = __expf(q0*kk.x + q1*kk.y - mx);
        float2 vv = sv[m];
        den += e;
        a0 += e*vv.x; a1 += e*vv.y;
    }
    float inv = 1.0f/den;
    g_att[(b*8 + 2*h  )*256 + t] = a0*inv;
    g_att[(b*8 + 2*h+1)*256 + t] = a1*inv;
}

// ---- K6: proj + residual + LN + MLP(exact gelu) + residual + GN2 + SiLU -> padded ----
__global__ void k_mlpapad(const float* __restrict__ wp, const float* __restrict__ bp,
                          const float* __restrict__ lng, const float* __restrict__ lnb,
                          const float* __restrict__ wf1, const float* __restrict__ bf1,
                          const float* __restrict__ wf2, const float* __restrict__ bf2,
                          const float* __restrict__ g2, const float* __restrict__ b2){
    __shared__ float sb[8];
    __shared__ float sm[8], sr[8];
    int b = blockIdx.x, t = threadIdx.x;
    float ao[8], z2[8];
    #pragma unroll
    for(int c=0;c<8;c++) ao[c] = g_att[(b*8+c)*256+t];
    #pragma unroll
    for(int c=0;c<8;c++){
        float s = bp[c] + g_z1[(b*8+c)*256+t];
        #pragma unroll
        for(int d=0;d<8;d++) s += wp[c*8+d]*ao[d];
        z2[c]=s;
    }
    float mu=0.f;
    #pragma unroll
    for(int c=0;c<8;c++) mu += z2[c];
    mu *= 0.125f;
    float var=0.f;
    #pragma unroll
    for(int c=0;c<8;c++){ float d=z2[c]-mu; var += d*d; }
    float rsl = rsqrtf(var*0.125f + EPSV);
    float ln[8];
    #pragma unroll
    for(int c=0;c<8;c++) ln[c] = (z2[c]-mu)*rsl*lng[c] + lnb[c];
    float hg[16];
    #pragma unroll
    for(int jj=0;jj<16;jj++){
        float s = bf1[jj];
        #pragma unroll
        for(int c=0;c<8;c++) s += wf1[jj*8+c]*ln[c];
        hg[jj] = 0.5f*s*(1.0f + erff(s*0.7071067811865475f));
    }
    float z3[8];
    #pragma unroll
    for(int c=0;c<8;c++){
        float s = z2[c] + bf2[c];
        #pragma unroll
        for(int jj=0;jj<16;jj++) s += wf2[c*16+jj]*hg[jj];
        z3[c]=s;
    }
    // GN2: stats on 16x16 equal stats on 4x4-upsampled tensor
    #pragma unroll
    for(int c=0;c<8;c++){
        float s  = redsum256(z3[c], sb);
        float s2 = redsum256(z3[c]*z3[c], sb);
        if(t==0){
            float m = s*(1.f/256.f);
            sm[c]=m; sr[c]=rsqrtf(s2*(1.f/256.f)-m*m+EPSV);
        }
    }
    __syncthreads();
    int Y=t>>4, X=t&15;
    #pragma unroll
    for(int c=0;c<8;c++){
        float a = siluf((z3[c]-sm[c])*sr[c]*g2[c] + b2[c]);
        g_apad[(b*8+c)*324 + (Y+1)*18 + (X+1)] = a;
    }
}

// ---- K7: collapse 3x3 conv weights into 6x6 stride-4 transposed-conv kernel ----
__global__ void k_wt(const float* __restrict__ w2){
    int idx = blockIdx.x*256+threadIdx.x;
    if(idx>=92160) return;
    int o = idx/288, r = idx-o*288, c = r/36, q = r-c*36, ky = q/6, kx = q-ky*6;
    int dy0 = max(0, 2-ky), dy1 = min(2, 5-ky);
    int dx0 = max(0, 2-kx), dx1 = min(2, 5-kx);
    float s=0.f;
    for(int dy=dy0;dy<=dy1;dy++)
        for(int dx=dx0;dx<=dx1;dx++)
            s += w2[o*72 + c*9 + dy*3 + dx];
    g_kw[idx] = s;
}

// ---- K8: fused upsample+conv2 (8->320) as stride-4 transposed conv ----
__global__ void __launch_bounds__(256) k_conv2(const float* __restrict__ bc2,
                                               float* __restrict__ out){
    __shared__ float sa[2592];   // a_pad[b]: 8 x 18 x 18
    __shared__ float sw[1152];   // collapsed weights for 4 o-channels
    int og = blockIdx.x, b = blockIdx.y;
    int t = threadIdx.x;
    for(int i=t;i<2592;i+=256) sa[i] = g_apad[b*2592+i];
    for(int i=t;i<1152;i+=256) sw[i] = g_kw[og*1152+i];
    __syncthreads();
    int ol = t>>6, u = t&63, Yq = u>>2, Xs = u&3;
    int o = og*4+ol;
    float bias = bc2[o];
    float acc[64];
    #pragma unroll
    for(int i=0;i<64;i++) acc[i]=bias;
    const int RYof[6]={3,0,1,2,3,0};
    const int RWof[6]={2,1,1,1,1,0};
    const int XL0[6] ={3,0,1,2,3,0};
    const int SCB[6] ={2,1,1,1,1,0};
    #pragma unroll
    for(int c=0;c<8;c++){
        float aw[3][6];
        #pragma unroll
        for(int r=0;r<3;r++)
            #pragma unroll
            for(int cc=0;cc<6;cc++)
                aw[r][cc] = sa[(c*18 + Yq + r)*18 + 4*Xs + cc];
        const float* wc = &sw[(ol*8 + c)*36];
        #pragma unroll
        for(int ky=0;ky<6;ky++){
            int ry = RYof[ky], riw = RWof[ky];
            #pragma unroll
            for(int kx=0;kx<6;kx++){
                float w = wc[ky*6+kx];
                int xl0 = XL0[kx], scb = SCB[kx];
                #pragma unroll
                for(int j=0;j<4;j++)
                    acc[ry*16 + xl0 + 4*j] += w * aw[riw][scb + j];
            }
        }
    }
    float4* ob = (float4*)(out + ((size_t)(b*320 + o)*64 + 4*Yq)*64 + 16*Xs);
    #pragma unroll
    for(int ry=0;ry<4;ry++)
        #pragma unroll
        for(int js=0;js<4;js++)
            ob[ry*16 + js] = make_float4(acc[ry*16+js*4], acc[ry*16+js*4+1],
                                         acc[ry*16+js*4+2], acc[ry*16+js*4+3]);
}

extern "C" void kernel_launch(void* const* d_in, const int* in_sizes, int n_in,
                              void* d_out, int out_size) {
    const float* x   = (const float*)d_in[0];
    const float* g1  = (const float*)d_in[1];
    const float* b1  = (const float*)d_in[2];
    const float* w1  = (const float*)d_in[3];
    const float* bc1 = (const float*)d_in[4];
    const float* ga  = (const float*)d_in[5];
    const float* ba  = (const float*)d_in[6];
    const float* wq  = (const float*)d_in[7];
    const float* bq  = (const float*)d_in[8];
    const float* wp  = (const float*)d_in[9];
    const float* bp  = (const float*)d_in[10];
    const float* lng = (const float*)d_in[11];
    const float* lnb = (const float*)d_in[12];
    const float* wf1 = (const float*)d_in[13];
    const float* bf1 = (const float*)d_in[14];
    const float* wf2 = (const float*)d_in[15];
    const float* bf2 = (const float*)d_in[16];
    const float* g2  = (const float*)d_in[17];
    const float* b2  = (const float*)d_in[18];
    const float* w2  = (const float*)d_in[19];
    const float* bc2 = (const float*)d_in[20];
    float* out = (float*)d_out;

    k_wt     <<<360, 256>>>(w2);
    k_pool   <<<5120, 256>>>(x);
    k_gstat  <<<512, 256>>>();
    k_conv1  <<<dim3(32,16), 256>>>(g1, b1, w1);
    k_qkv    <<<16, 256>>>(bc1, ga, ba, wq, bq);
    k_attn   <<<64, 256>>>();
    k_mlpapad<<<16, 256>>>(wp, bp, lng, lnb, wf1, bf1, wf2, bf2, g2, b2);
    k_conv2  <<<dim3(80,16), 256>>>(bc2, out);
}